// round 7
// baseline (speedup 1.0000x reference)
#include <cuda_runtime.h>
#include <math.h>

// VolatilityLoss: mean((std3(pred) - std3(targ))^2), window w=3.
// B=512, S=8192, L=8190 outputs/row.
// Difference-chain form: 6*var_i = e_i^2 + e_{i+1}^2 + (e_i+e_{i+1})^2,
// e_i = x_i - x_{i+1}; pair combined with one sqrt:
// (sqrt(vp)-sqrt(vt))^2 = (vp6 + vt6 - 2*sqrt(vp6*vt6)) / 6.
// 16 contiguous outputs/thread, 8 front-batched LDG.128, fused finalize.

#define B_ROWS 512
#define S_LEN  8192
#define L_OUT  (S_LEN - 2)            // 8190
#define NBLOCKS 1024
#define NTHREADS 256
// NBLOCKS*NTHREADS*16 == B_ROWS*S_LEN exactly (one 16-span per thread)

__device__ float        g_partials[NBLOCKS];
__device__ unsigned int g_counter = 0;   // monotone across graph replays

__device__ __forceinline__ float sqrt_approx(float x) {
    float r;
    asm("sqrt.approx.f32 %0, %1;" : "=f"(r) : "f"(x));
    return r;
}

__global__ void __launch_bounds__(NTHREADS)
vol_loss_fused(const float* __restrict__ pred, const float* __restrict__ targ,
               float* __restrict__ out) {
    const int g    = blockIdx.x * NTHREADS + threadIdx.x;
    const int lane = threadIdx.x & 31;
    const int row   = g >> 9;            // 512 16-spans per row
    const int start = (g & 511) << 4;

    const float* pb = pred + ((size_t)row << 13) + start;
    const float* tb = targ + ((size_t)row << 13) + start;

    // 8 independent LDG.128, front-batched.
    float4 pA = ((const float4*)pb)[0];
    float4 pB = ((const float4*)pb)[1];
    float4 pC = ((const float4*)pb)[2];
    float4 pD = ((const float4*)pb)[3];
    float4 tA = ((const float4*)tb)[0];
    float4 tB = ((const float4*)tb)[1];
    float4 tC = ((const float4*)tb)[2];
    float4 tD = ((const float4*)tb)[3];

    // Elements 16,17 of my span = lane+1's elements 0,1. Lane 31 loads them
    // (predicated off at the row end, where windows 14,15 are invalid anyway).
    bool full = (start + 16) < S_LEN;    // false only for last span of a row (lane 31)
    float p16 = __shfl_down_sync(0xffffffffu, pA.x, 1);
    float p17 = __shfl_down_sync(0xffffffffu, pA.y, 1);
    float t16 = __shfl_down_sync(0xffffffffu, tA.x, 1);
    float t17 = __shfl_down_sync(0xffffffffu, tA.y, 1);
    if (lane == 31) {
        p16 = p17 = t16 = t17 = 0.0f;
        if (full) {
            float2 pe2 = ((const float2*)(pb + 16))[0];
            float2 te2 = ((const float2*)(tb + 16))[0];
            p16 = pe2.x; p17 = pe2.y; t16 = te2.x; t17 = te2.y;
        }
    }

    const float pe[18] = {pA.x, pA.y, pA.z, pA.w, pB.x, pB.y, pB.z, pB.w,
                          pC.x, pC.y, pC.z, pC.w, pD.x, pD.y, pD.z, pD.w,
                          p16, p17};
    const float te[18] = {tA.x, tA.y, tA.z, tA.w, tB.x, tB.y, tB.z, tB.w,
                          tC.x, tC.y, tC.z, tC.w, tD.x, tD.y, tD.z, tD.w,
                          t16, t17};

    // Rolling difference chain (accumulates 6*MSE contribution).
    float acc = 0.0f;
    float epp = pe[0] - pe[1];  float gpp = epp * epp;
    float ept = te[0] - te[1];  float gpt = ept * ept;
    #pragma unroll
    for (int j = 0; j < 16; ++j) {
        float ep = pe[j + 1] - pe[j + 2];  float gp = ep * ep;
        float et = te[j + 1] - te[j + 2];  float gt = et * et;
        float fp = epp + ep;
        float ft = ept + et;
        float vp = fmaf(fp, fp, gpp + gp);   // = 6*var_pred, >= 0
        float vt = fmaf(ft, ft, gpt + gt);   // = 6*var_targ, >= 0
        if (j < 14 || full)
            acc += (vp + vt) - 2.0f * sqrt_approx(vp * vt);
        epp = ep; gpp = gp; ept = et; gpt = gt;
    }

    // Deterministic intra-block reduction.
    #pragma unroll
    for (int o = 16; o > 0; o >>= 1)
        acc += __shfl_down_sync(0xffffffffu, acc, o);

    __shared__ float red[NTHREADS / 32];
    int warp = threadIdx.x >> 5;
    if (lane == 0) red[warp] = acc;
    __syncthreads();

    __shared__ bool is_last;
    if (threadIdx.x == 0) {
        float v = 0.0f;
        #pragma unroll
        for (int w = 0; w < NTHREADS / 32; ++w) v += red[w];
        g_partials[blockIdx.x] = v;
        __threadfence();
        unsigned int old = atomicAdd(&g_counter, 1u);
        is_last = ((old + 1u) % (unsigned)NBLOCKS) == 0u;
    }
    __syncthreads();

    if (!is_last) return;

    // Last block: deterministic final reduction; fold the deferred /6 here.
    __shared__ double sh[NTHREADS];
    double s = 0.0;
    for (int i = threadIdx.x; i < NBLOCKS; i += NTHREADS)
        s += (double)g_partials[i];
    sh[threadIdx.x] = s;
    __syncthreads();
    #pragma unroll
    for (int stride = NTHREADS / 2; stride > 0; stride >>= 1) {
        if (threadIdx.x < stride) sh[threadIdx.x] += sh[threadIdx.x + stride];
        __syncthreads();
    }
    if (threadIdx.x == 0)
        out[0] = (float)(sh[0] / (6.0 * (double)B_ROWS * (double)L_OUT));
}

extern "C" void kernel_launch(void* const* d_in, const int* in_sizes, int n_in,
                              void* d_out, int out_size) {
    const float* pred = (const float*)d_in[0];
    const float* targ = (const float*)d_in[1];
    vol_loss_fused<<<NBLOCKS, NTHREADS>>>(pred, targ, (float*)d_out);
}